// round 7
// baseline (speedup 1.0000x reference)
#include <cuda_runtime.h>
#include <math.h>

#define Bc 8
#define Nc 4096
#define Dc 768
#define Ec 8
#define ESc 16
#define Hc 3072
#define NCH1 64
#define TOK1 64
#define TOK7 64

typedef unsigned long long u64;
typedef unsigned int u32;

// ----------------- scratch -----------------
__device__ float g_logits[Bc * Nc * ESc];
__device__ float g_pxs[Bc * NCH1 * ESc * Dc];
__device__ __align__(16) u64 g_xs2[Ec * Dc * 8];       // [e][d][rp]
__device__ float g_mch[Bc * NCH1 * ESc];
__device__ float g_sch[Bc * NCH1 * ESc];
__device__ float g_cmaxf[Bc * ESc];
__device__ float g_inv[Bc * ESc];
__device__ __align__(16) u64 g_h2p[2 * Ec * Hc * 8];   // d-half partials
__device__ __align__(16) u64 g_h2[Ec * Hc * 8];        // [e][f][rp]
__device__ float g_ys[Bc * ESc * Dc];

// ----------------- f32x2 helpers -----------------
__device__ __forceinline__ u64 pk2(float x, float y) {
    u64 r; asm("mov.b64 %0, {%1, %2};" : "=l"(r) : "f"(x), "f"(y)); return r;
}
__device__ __forceinline__ u64 dup2(float x) {
    u64 r; asm("mov.b64 %0, {%1, %1};" : "=l"(r) : "f"(x)); return r;
}
__device__ __forceinline__ void up2(u64 v, float& x, float& y) {
    asm("mov.b64 {%0, %1}, %2;" : "=f"(x), "=f"(y) : "l"(v));
}
__device__ __forceinline__ void fma2(u64& d, u64 a, u64 b) {
    asm("fma.rn.f32x2 %0, %1, %2, %0;" : "+l"(d) : "l"(a), "l"(b));
}
__device__ __forceinline__ u64 add2(u64 a, u64 b) {
    u64 r; asm("add.rn.f32x2 %0, %1, %2;" : "=l"(r) : "l"(a), "l"(b)); return r;
}
__device__ __forceinline__ float gelu_exact(float v) {
    return 0.5f * v * (1.0f + erff(v * 0.70710678118654752f));
}

// ---- k1 smem float offsets (total 43.3KB -> 3 blocks/SM with regs) ----
#define OFF_XT    0                      // 64 x 65 = 4160
#define OFF_PHIB  4160                   // 1024 floats (512 u64, one 64-d block)
#define OFF_RED   5184                   // 1536 u64 = 3072 floats
#define OFF_LSM   8256                   // 64 x 16
#define OFF_DSM   9280                   // 64 x 16
#define OFF_GM    10304                  // 16 x 16
#define OFF_PS    10560                  // 16 x 16
#define OFF_CM    10816                  // 16
#define K1_SMEM_FLOATS 10832             // 43328 B

// ================= K1: fused logits + dispatch softmax + chunk colstats + partial xs ===
// grid (64, 8), 256 thr
extern "C" __global__ void __launch_bounds__(256, 3)
k1_fused(const float* __restrict__ x, const float* __restrict__ phi) {
    extern __shared__ float smemf[];
    float* xT   = smemf + OFF_XT;
    float* phiB = smemf + OFF_PHIB;
    u64*   red  = (u64*)(smemf + OFF_RED);
    float* lsm  = smemf + OFF_LSM;
    float* dsm  = smemf + OFF_DSM;
    float* gm   = smemf + OFF_GM;
    float* ps   = smemf + OFF_PS;
    float* cm   = smemf + OFF_CM;

    const int b = blockIdx.y, chunk = blockIdx.x;
    const int tid = threadIdx.x;
    const float* xc = x + ((size_t)b * Nc + chunk * TOK1) * Dc;

    // ---- Phase A: logits. thread = (tok 0..63, seg 0..3); seg = 16 d per 64-d block ---
    const int tok = tid & 63;
    const int seg = tid >> 6;
    u64 acc[8];
    #pragma unroll
    for (int j = 0; j < 8; ++j) acc[j] = 0ull;

    for (int db = 0; db < 12; ++db) {
        const int d0 = db * 64;
        __syncthreads();
        // stage x[64 tok][64 d] transposed via float4 loads
        #pragma unroll
        for (int k = 0; k < 4; ++k) {
            const int idx = tid + k * 256;          // 0..1023
            const int t = idx >> 4, dd4 = idx & 15;
            const float4 v = __ldg((const float4*)(xc + (size_t)t * Dc + d0 + dd4 * 4));
            xT[(dd4 * 4 + 0) * 65 + t] = v.x;
            xT[(dd4 * 4 + 1) * 65 + t] = v.y;
            xT[(dd4 * 4 + 2) * 65 + t] = v.z;
            xT[(dd4 * 4 + 3) * 65 + t] = v.w;
        }
        // stage phi rows [d0, d0+64): 1024 floats = 256 float4 (L2-hot after 1st block)
        ((float4*)phiB)[tid] = __ldg(((const float4*)(phi + (size_t)d0 * ESc)) + tid);
        __syncthreads();
        const ulonglong2* pp = (const ulonglong2*)phiB;
        #pragma unroll 4
        for (int i = 0; i < 16; ++i) {
            const int dd = seg * 16 + i;
            const u64 xd = dup2(xT[dd * 65 + tok]);
            ulonglong2 q0 = pp[dd * 4 + 0];
            ulonglong2 q1 = pp[dd * 4 + 1];
            ulonglong2 q2 = pp[dd * 4 + 2];
            ulonglong2 q3 = pp[dd * 4 + 3];
            fma2(acc[0], xd, q0.x); fma2(acc[1], xd, q0.y);
            fma2(acc[2], xd, q1.x); fma2(acc[3], xd, q1.y);
            fma2(acc[4], xd, q2.x); fma2(acc[5], xd, q2.y);
            fma2(acc[6], xd, q3.x); fma2(acc[7], xd, q3.y);
        }
    }
    __syncthreads();
    if (seg > 0) {
        u64* r = red + ((seg - 1) * 64 + tok) * 8;
        #pragma unroll
        for (int j = 0; j < 8; ++j) r[j] = acc[j];
    }
    __syncthreads();
    if (seg == 0) {
        #pragma unroll
        for (int q = 0; q < 3; ++q) {
            const u64* r = red + (q * 64 + tok) * 8;
            #pragma unroll
            for (int j = 0; j < 8; ++j) acc[j] = add2(acc[j], r[j]);
        }
        float l[16];
        #pragma unroll
        for (int j = 0; j < 8; ++j) up2(acc[j], l[2 * j], l[2 * j + 1]);
        float m = l[0];
        #pragma unroll
        for (int es = 1; es < 16; ++es) m = fmaxf(m, l[es]);
        float s = 0.f;
        float p[16];
        #pragma unroll
        for (int es = 0; es < 16; ++es) { p[es] = __expf(l[es] - m); s += p[es]; }
        const float inv = 1.f / s;
        u64* dl = (u64*)dsm;
        u64* ll = (u64*)lsm;
        #pragma unroll
        for (int j = 0; j < 8; ++j) {
            dl[tok * 8 + j] = pk2(p[2 * j] * inv, p[2 * j + 1] * inv);
            ll[tok * 8 + j] = pk2(l[2 * j], l[2 * j + 1]);
        }
    }
    __syncthreads();

    {   // raw logits -> global
        const size_t lbase = ((size_t)b * Nc + chunk * TOK1) * ESc;
        #pragma unroll
        for (int k = 0; k < 4; ++k) g_logits[lbase + tid + k * 256] = lsm[tid + k * 256];
    }

    // ---- Phase B: per-chunk column stats (16 groups x 4 tokens) ----
    {
        const int g = tid >> 4, es = tid & 15;
        float m = -1e30f;
        #pragma unroll
        for (int t4 = 0; t4 < 4; ++t4) m = fmaxf(m, lsm[(g * 4 + t4) * ESc + es]);
        gm[g * 16 + es] = m;
    }
    __syncthreads();
    if (tid < 16) {
        float m = gm[tid];
        #pragma unroll
        for (int g = 1; g < 16; ++g) m = fmaxf(m, gm[g * 16 + tid]);
        cm[tid] = m;
    }
    __syncthreads();
    {
        const int g = tid >> 4, es = tid & 15;
        const float m = cm[es];
        float p = 0.f;
        #pragma unroll
        for (int t4 = 0; t4 < 4; ++t4) p += __expf(lsm[(g * 4 + t4) * ESc + es] - m);
        ps[g * 16 + es] = p;
    }
    __syncthreads();
    if (tid < 16) {
        float s = 0.f;
        #pragma unroll
        for (int g = 0; g < 16; ++g) s += ps[g * 16 + tid];
        g_mch[((size_t)b * NCH1 + chunk) * ESc + tid] = cm[tid];
        g_sch[((size_t)b * NCH1 + chunk) * ESc + tid] = s;
    }

    // ---- Phase C: partial xs, thread = (12 d as 3 float4) x (4 es) ----
    {
        const int f4i = tid & 63;
        const int esq = tid >> 6;
        u64 acc2[4][3][2];
        #pragma unroll
        for (int e = 0; e < 4; ++e)
            #pragma unroll
            for (int j = 0; j < 3; ++j) { acc2[e][j][0] = 0ull; acc2[e][j][1] = 0ull; }

        const int dbase = f4i * 4;
        #pragma unroll 2
        for (int t = 0; t < TOK1; ++t) {
            const float4 xv0 = __ldg((const float4*)(xc + (size_t)t * Dc + dbase));
            const float4 xv1 = __ldg((const float4*)(xc + (size_t)t * Dc + dbase + 256));
            const float4 xv2 = __ldg((const float4*)(xc + (size_t)t * Dc + dbase + 512));
            const u64 x0l = pk2(xv0.x, xv0.y), x0h = pk2(xv0.z, xv0.w);
            const u64 x1l = pk2(xv1.x, xv1.y), x1h = pk2(xv1.z, xv1.w);
            const u64 x2l = pk2(xv2.x, xv2.y), x2h = pk2(xv2.z, xv2.w);
            const float4 dv = *(const float4*)&dsm[t * ESc + esq * 4];
            const u64 w0 = dup2(dv.x), w1 = dup2(dv.y), w2 = dup2(dv.z), w3 = dup2(dv.w);
            fma2(acc2[0][0][0], w0, x0l); fma2(acc2[0][0][1], w0, x0h);
            fma2(acc2[0][1][0], w0, x1l); fma2(acc2[0][1][1], w0, x1h);
            fma2(acc2[0][2][0], w0, x2l); fma2(acc2[0][2][1], w0, x2h);
            fma2(acc2[1][0][0], w1, x0l); fma2(acc2[1][0][1], w1, x0h);
            fma2(acc2[1][1][0], w1, x1l); fma2(acc2[1][1][1], w1, x1h);
            fma2(acc2[1][2][0], w1, x2l); fma2(acc2[1][2][1], w1, x2h);
            fma2(acc2[2][0][0], w2, x0l); fma2(acc2[2][0][1], w2, x0h);
            fma2(acc2[2][1][0], w2, x1l); fma2(acc2[2][1][1], w2, x1h);
            fma2(acc2[2][2][0], w2, x2l); fma2(acc2[2][2][1], w2, x2h);
            fma2(acc2[3][0][0], w3, x0l); fma2(acc2[3][0][1], w3, x0h);
            fma2(acc2[3][1][0], w3, x1l); fma2(acc2[3][1][1], w3, x1h);
            fma2(acc2[3][2][0], w3, x2l); fma2(acc2[3][2][1], w3, x2h);
        }
        float* out = g_pxs + ((size_t)(b * NCH1 + chunk) * ESc) * Dc;
        #pragma unroll
        for (int e = 0; e < 4; ++e) {
            const int es = esq * 4 + e;
            #pragma unroll
            for (int j = 0; j < 3; ++j) {
                float4 o;
                up2(acc2[e][j][0], o.x, o.y);
                up2(acc2[e][j][1], o.z, o.w);
                *(float4*)(out + (size_t)es * Dc + dbase + 256 * j) = o;
            }
        }
    }
}

// ================= K2: reduce xs partials + pack row pairs =================
__global__ void __launch_bounds__(256) k2_reduce_xs() {
    const int idx = blockIdx.x * 256 + threadIdx.x;
    const int b = idx / (ESc * Dc);
    const int rem = idx % (ESc * Dc);
    const int es = rem / Dc, d = rem % Dc;
    float s = 0.f;
    #pragma unroll 8
    for (int c = 0; c < NCH1; ++c)
        s += g_pxs[((size_t)(b * NCH1 + c)) * (ESc * Dc) + rem];
    const int e = es >> 1, sl = es & 1, row = b * 2 + sl;
    ((float*)g_xs2)[((size_t)e * Dc + d) * 16 + row] = s;
}

// ================= K4: finalize colmax / inv colsum =================
__global__ void k4_finalize() {
    const int i = threadIdx.x;
    if (i >= Bc * ESc) return;
    const int b = i >> 4, es = i & 15;
    float M = -1e30f;
    #pragma unroll 8
    for (int c = 0; c < NCH1; ++c)
        M = fmaxf(M, g_mch[((size_t)b * NCH1 + c) * ESc + es]);
    float S = 0.f;
    #pragma unroll 8
    for (int c = 0; c < NCH1; ++c) {
        const size_t o = ((size_t)b * NCH1 + c) * ESc + es;
        S += __expf(g_mch[o] - M) * g_sch[o];
    }
    g_cmaxf[i] = M;
    g_inv[i] = 1.f / S;
}

// ================= K5a: FFN1 partial (grid (48, 8, 2), 256 thr) =================
// z = d-half. thread: fi=t&15 (4 f), rh=(t>>4)&1 (4 row-pairs), ds=t>>5 (8 segs of 48 d)
#define K5_SMEM_BYTES (384 * 8 * 8 + 2048 * 8)   // 24576 + 16384 = 40960
__global__ void __launch_bounds__(256, 4)
k5_ffn1(const float* __restrict__ w1) {
    extern __shared__ __align__(16) char k5smem[];
    u64* xsm = (u64*)k5smem;             // 384*8
    u64* red = xsm + 384 * 8;            // 2048
    const int e = blockIdx.y;
    const int fbase = blockIdx.x * 64;
    const int z = blockIdx.z;
    const int tid = threadIdx.x;
    {
        const ulonglong2* src = (const ulonglong2*)(g_xs2 + ((size_t)e * Dc + z * 384) * 8);
        ulonglong2* dst = (ulonglong2*)xsm;
        #pragma unroll
        for (int k = 0; k < 6; ++k) dst[tid + k * 256] = src[tid + k * 256];
    }
    __syncthreads();

    const int fi = tid & 15;
    const int rh = (tid >> 4) & 1;
    const int ds = tid >> 5;
    const int lid32 = tid & 31;
    const int f = fbase + fi * 4;

    u64 acc[4][4];
    #pragma unroll
    for (int j = 0; j < 4; ++j)
        #pragma unroll
        for (int r = 0; r < 4; ++r) acc[j][r] = 0ull;

    const float* w = w1 + ((size_t)e * Dc + z * 384) * Hc + f;
    const ulonglong2* x2 = (const ulonglong2*)xsm;
    const int dlo = ds * 48;
    #pragma unroll 4
    for (int d = dlo; d < dlo + 48; ++d) {
        const float4 wv = __ldg((const float4*)(w + (size_t)d * Hc));
        const ulonglong2 xa = x2[d * 4 + rh * 2];
        const ulonglong2 xb = x2[d * 4 + rh * 2 + 1];
        const u64 w0 = dup2(wv.x), w1d = dup2(wv.y), w2 = dup2(wv.z), w3 = dup2(wv.w);
        fma2(acc[0][0], w0, xa.x); fma2(acc[0][1], w0, xa.y);
        fma2(acc[0][2], w0, xb.x); fma2(acc[0][3], w0, xb.y);
        fma2(acc[1][0], w1d, xa.x); fma2(acc[1][1], w1d, xa.y);
        fma2(acc[1][2], w1d, xb.x); fma2(acc[1][3], w1d, xb.y);
        fma2(acc[2][0], w2, xa.x); fma2(acc[2][1], w2, xa.y);
        fma2(acc[2][2], w2, xb.x); fma2(acc[2][3], w2, xb.y);
        fma2(acc[3][0], w3, xa.x); fma2(acc[3][1], w3, xa.y);
        fma2(acc[3][2], w3, xb.x); fma2(acc[3][3], w3, xb.y);
    }

    // tree reduce over 8 d-segs
    if (ds >= 4) {
        u64* r = red + ((ds - 4) * 32 + lid32) * 16;
        #pragma unroll
        for (int j = 0; j < 4; ++j)
            #pragma unroll
            for (int k = 0; k < 4; ++k) r[j * 4 + k] = acc[j][k];
    }
    __syncthreads();
    if (ds < 4) {
        const u64* r = red + (ds * 32 + lid32) * 16;
        #pragma unroll
        for (int j = 0; j < 4; ++j)
            #pragma unroll
            for (int k = 0; k < 4; ++k) acc[j][k] = add2(acc[j][k], r[j * 4 + k]);
    }
    __syncthreads();
    if (ds >= 2 && ds < 4) {
        u64* r = red + ((ds - 2) * 32 + lid32) * 16;
        #pragma unroll
        for (int j = 0; j < 4; ++j)
            #pragma unroll
            for (int k = 0; k < 4; ++k) r[j * 4 + k] = acc[j][k];
    }
    __syncthreads();
    if (ds < 2) {
        const u64* r = red + (ds * 32 + lid32) * 16;
        #pragma unroll
        for (int j = 0; j < 4; ++j)
            #pragma unroll
            for (int k = 0; k < 4; ++k) acc[j][k] = add2(acc[j][k], r[j * 4 + k]);
    }
    __syncthreads();
    if (ds == 1) {
        u64* r = red + lid32 * 16;
        #pragma unroll
        for (int j = 0; j < 4; ++j)
            #pragma unroll
            for (int k = 0; k < 4; ++k) r[j * 4 + k] = acc[j][k];
    }
    __syncthreads();
    if (ds == 0) {
        const u64* r = red + lid32 * 16;
        #pragma unroll
        for (int j = 0; j < 4; ++j) {
            #pragma unroll
            for (int k = 0; k < 4; ++k) {
                const u64 v = add2(acc[j][k], r[j * 4 + k]);
                g_h2p[(((size_t)z * Ec + e) * Hc + f + j) * 8 + rh * 4 + k] = v;
            }
        }
    }
}

// ================= K5b: combine halves + bias + GELU (grid 384) =================
__global__ void __launch_bounds__(256) k5b_gelu(const float* __restrict__ b1) {
    const int i = blockIdx.x * 256 + threadIdx.x;      // 0..98303 (ulonglong2 units)
    const ulonglong2* p0 = (const ulonglong2*)g_h2p;
    const ulonglong2* p1 = p0 + (Ec * Hc * 8) / 2;
    const ulonglong2 a = p0[i], b = p1[i];
    const u64 s0 = add2(a.x, b.x), s1 = add2(a.y, b.y);
    const int fg = i >> 2;                             // global f index (e*Hc+f)
    const float bv = __ldg(b1 + fg);
    float l0, h0, l1, h1;
    up2(s0, l0, h0); up2(s1, l1, h1);
    ulonglong2 o;
    o.x = pk2(gelu_exact(l0 + bv), gelu_exact(h0 + bv));
    o.y = pk2(gelu_exact(l1 + bv), gelu_exact(h1 + bv));
    ((ulonglong2*)g_h2)[i] = o;
}

// ================= K6: FFN2 + bias  (grid (96, 8), 256 thr) =================
// thread: dq=t&1 (4 d), rh=(t>>1)&1 (4 row-pairs), fs=t>>2 (64 f-slices of 48)
__global__ void __launch_bounds__(256)
k6_ffn2(const float* __restrict__ w2, const float* __restrict__ b2) {
    __shared__ __align__(16) u64 red[64 * 64 + 256];   // 34KB
    const int e = blockIdx.y;
    const int d0 = blockIdx.x * 8;
    const int tid = threadIdx.x;
    const int dq = tid & 1, rh = (tid >> 1) & 1, fs = tid >> 2;

    u64 acc[4][4];
    #pragma unroll
    for (int j = 0; j < 4; ++j)
        #pragma unroll
        for (int r = 0; r < 4; ++r) acc[j][r] = 0ull;

    const float* w = w2 + (size_t)e * Hc * Dc + d0 + dq * 4;
    const ulonglong2* h2 = (const ulonglong2*)(g_h2 + (size_t)e * Hc * 8);
    const int f0 = fs * 48;
    #pragma unroll 4
    for (int f = f0; f < f0 + 48; ++f) {
        const float4 wv = __ldg((const float4*)(w + (size_t)f * Dc));
        const ulonglong2 ha = h2[f * 4 + rh * 2];
        const ulonglong2 hb = h2[f * 4 + rh * 2 + 1];
        const u64 wd0 = dup2(wv.x), wd1 = dup2(wv.y), wd2 = dup2(wv.z), wd3 = dup2(wv.w);
        fma2(acc[0][0], wd0, ha.x); fma2(acc[0][1], wd0, ha.y);
        fma2(acc[0][2], wd0, hb.x); fma2(acc[0][3], wd0, hb.y);
        fma2(acc[1][0], wd1, ha.x); fma2(acc[1][1], wd1, ha.y);
        fma2(acc[1][2], wd1, hb.x); fma2(acc[1][3], wd1, hb.y);
        fma2(acc[2][0], wd2, ha.x); fma2(acc[2][1], wd2, ha.y);
        fma2(acc[2][2], wd2, hb.x); fma2(acc[2][3], wd2, hb.y);
        fma2(acc[3][0], wd3, ha.x); fma2(acc[3][1], wd3, ha.y);
        fma2(acc[3][2], wd3, hb.x); fma2(acc[3][3], wd3, hb.y);
    }
    #pragma unroll
    for (int j = 0; j < 4; ++j)
        #pragma unroll
        for (int r = 0; r < 4; ++r)
            red[fs * 64 + (dq * 4 + j) * 8 + rh * 4 + r] = acc[j][r];
    __syncthreads();
    // stage 1: 4 quarter-sums over 16 slices each
    u64* red2 = red + 64 * 64;
    {
        const int q = tid >> 6, i64 = tid & 63;
        u64 s = red[(q * 16) * 64 + i64];
        #pragma unroll
        for (int sl = 1; sl < 16; ++sl) s = add2(s, red[(q * 16 + sl) * 64 + i64]);
        red2[q * 64 + i64] = s;
    }
    __syncthreads();
    if (tid < 64) {
        u64 s = add2(add2(red2[tid], red2[64 + tid]), add2(red2[128 + tid], red2[192 + tid]));
        float lo, hi; up2(s, lo, hi);
        const int d_loc = tid >> 3, rp = tid & 7;
        const float bb2 = __ldg(b2 + (size_t)e * Dc + d0 + d_loc);
        const int r0 = 2 * rp, r1 = 2 * rp + 1;
        g_ys[((size_t)(r0 >> 1) * ESc + e * 2 + (r0 & 1)) * Dc + d0 + d_loc] = lo + bb2;
        g_ys[((size_t)(r1 >> 1) * ESc + e * 2 + (r1 & 1)) * Dc + d0 + d_loc] = hi + bb2;
    }
}

// ================= K7: combine softmax + y = c @ ys  (grid (64, 8)) =================
#define K7_SMEM_FLOATS (ESc * Dc + ESc * TOK7 + 32)
extern "C" __global__ void __launch_bounds__(256)
k7_combine(float* __restrict__ y) {
    extern __shared__ float smemf[];
    float* ysm = smemf;                       // [16][768]
    float* csm = smemf + ESc * Dc;            // [16][64]
    float* cm  = smemf + ESc * Dc + ESc * TOK7;
    float* inv = cm + 16;

    const int b = blockIdx.y, chunk = blockIdx.x, tid = threadIdx.x;
    {
        const float4* src = (const float4*)(g_ys + (size_t)b * ESc * Dc);
        float4* dst = (float4*)ysm;
        #pragma unroll
        for (int k = 0; k < 12; ++k) dst[tid + k * 256] = src[tid + k * 256];
    }
    if (tid < 16) { cm[tid] = g_cmaxf[b * ESc + tid]; inv[tid] = g_inv[b * ESc + tid]; }
    __syncthreads();

    {   // combine weights: 1024 entries, 4 per thread
        const int i0 = tid * 4;
        const int es = i0 >> 6;
        const int t0 = i0 & 63;
        const float m = cm[es], iv = inv[es];
        const float* lp = g_logits + ((size_t)b * Nc + chunk * TOK7 + t0) * ESc + es;
        #pragma unroll
        for (int q = 0; q < 4; ++q)
            csm[es * TOK7 + t0 + q] = __expf(lp[q * ESc] - m) * iv;
    }
    __syncthreads();

    const int dg = tid & 63, tg = tid >> 6;
    const int dbase = dg * 4;
    float* yb = y + ((size_t)b * Nc + chunk * TOK7) * Dc;
    for (int tq = 0; tq < 4; ++tq) {
        const int trel = tg * 16 + tq * 4;
        u64 acc[4][3][2];
        #pragma unroll
        for (int t = 0; t < 4; ++t)
            #pragma unroll
            for (int j = 0; j < 3; ++j) { acc[t][j][0] = 0ull; acc[t][j][1] = 0ull; }
        #pragma unroll
        for (int es = 0; es < 16; ++es) {
            float4 c4 = *(const float4*)&csm[es * TOK7 + trel];
            u64 cd0 = dup2(c4.x), cd1 = dup2(c4.y), cd2 = dup2(c4.z), cd3 = dup2(c4.w);
            #pragma unroll
            for (int j = 0; j < 3; ++j) {
                float4 yv = *(const float4*)&ysm[es * Dc + dbase + 256 * j];
                u64 ylo = pk2(yv.x, yv.y), yhi = pk2(yv.z, yv.w);
                fma2(acc[0][j][0], cd0, ylo); fma2(acc[0][j][1], cd0, yhi);
                fma2(acc[1][j][0], cd1, ylo); fma2(acc[1][j][1], cd1, yhi);
                fma2(acc[2][j][0], cd2, ylo); fma2(acc[2][j][1], cd2, yhi);
                fma2(acc[3][j][0], cd3, ylo); fma2(acc[3][j][1], cd3, yhi);
            }
        }
        #pragma unroll
        for (int t = 0; t < 4; ++t) {
            float* yr = yb + (size_t)(trel + t) * Dc;
            #pragma unroll
            for (int j = 0; j < 3; ++j) {
                float4 o;
                up2(acc[t][j][0], o.x, o.y);
                up2(acc[t][j][1], o.z, o.w);
                *(float4*)(yr + dbase + 256 * j) = o;
            }
        }
    }
}

// ================= host =================
extern "C" void kernel_launch(void* const* d_in, const int* in_sizes, int n_in,
                              void* d_out, int out_size) {
    const float* x   = (const float*)d_in[0];
    const float* phi = (const float*)d_in[1];
    const float* w1  = (const float*)d_in[2];
    const float* b1  = (const float*)d_in[3];
    const float* w2  = (const float*)d_in[4];
    const float* b2  = (const float*)d_in[5];
    float* y = (float*)d_out;

    cudaFuncSetAttribute(k1_fused, cudaFuncAttributeMaxDynamicSharedMemorySize,
                         K1_SMEM_FLOATS * sizeof(float));
    cudaFuncSetAttribute(k5_ffn1, cudaFuncAttributeMaxDynamicSharedMemorySize,
                         K5_SMEM_BYTES);
    cudaFuncSetAttribute(k7_combine, cudaFuncAttributeMaxDynamicSharedMemorySize,
                         K7_SMEM_FLOATS * sizeof(float));
    (void)in_sizes; (void)n_in; (void)out_size;

    k1_fused<<<dim3(NCH1, Bc), 256, K1_SMEM_FLOATS * sizeof(float)>>>(x, phi);
    k2_reduce_xs<<<(Bc * ESc * Dc) / 256, 256>>>();
    k4_finalize<<<1, 128>>>();
    k5_ffn1<<<dim3(48, Ec, 2), 256, K5_SMEM_BYTES>>>(w1);
    k5b_gelu<<<384, 256>>>(b1);
    k6_ffn2<<<dim3(96, Ec), 256>>>(w2, b2);
    k7_combine<<<dim3(Nc / TOK7, Bc), 256, K7_SMEM_FLOATS * sizeof(float)>>>(y);
}

// round 8
// speedup vs baseline: 1.2614x; 1.2614x over previous
#include <cuda_runtime.h>
#include <math.h>

#define Bc 8
#define Nc 4096
#define Dc 768
#define Ec 8
#define ESc 16
#define Hc 3072
#define NCH1 64
#define TOK1 64
#define TOK7 64

typedef unsigned long long u64;
typedef unsigned int u32;

// ----------------- scratch -----------------
__device__ float g_logits[Bc * Nc * ESc];
__device__ float g_pxs[Bc * NCH1 * ESc * Dc];          // 25.2 MB
__device__ __align__(16) u64 g_xs2[Ec * Dc * 8];       // [e][d][rp]
__device__ float g_mch[Bc * NCH1 * ESc];
__device__ float g_sch[Bc * NCH1 * ESc];
__device__ float g_cmaxf[Bc * ESc];
__device__ float g_inv[Bc * ESc];
__device__ __align__(16) u64 g_h2[Ec * Hc * 8];        // [e][f][rp]
__device__ float g_ys[Bc * ESc * Dc];

// ----------------- f32x2 helpers -----------------
__device__ __forceinline__ u64 pk2(float x, float y) {
    u64 r; asm("mov.b64 %0, {%1, %2};" : "=l"(r) : "f"(x), "f"(y)); return r;
}
__device__ __forceinline__ u64 dup2(float x) {
    u64 r; asm("mov.b64 %0, {%1, %1};" : "=l"(r) : "f"(x)); return r;
}
__device__ __forceinline__ void up2(u64 v, float& x, float& y) {
    asm("mov.b64 {%0, %1}, %2;" : "=f"(x), "=f"(y) : "l"(v));
}
__device__ __forceinline__ void fma2(u64& d, u64 a, u64 b) {
    asm("fma.rn.f32x2 %0, %1, %2, %0;" : "+l"(d) : "l"(a), "l"(b));
}
__device__ __forceinline__ u64 add2(u64 a, u64 b) {
    u64 r; asm("add.rn.f32x2 %0, %1, %2;" : "=l"(r) : "l"(a), "l"(b)); return r;
}
__device__ __forceinline__ float gelu_exact(float v) {
    return 0.5f * v * (1.0f + erff(v * 0.70710678118654752f));
}

// ---- k1 smem float offsets ----
#define OFF_PHI  0                      // 12288 floats (u64[768*8])
#define OFF_XT   12288                  // 64 x 65 = 4160
#define OFF_RED  16448                  // 1536 u64 = 3072 floats
#define OFF_LSM  19520                  // 64 x 16
#define OFF_DSM  20544                  // 64 x 16
#define OFF_GM   21568                  // 16 x 16
#define OFF_PS   21824                  // 16 x 16
#define OFF_CM   22080                  // 16
#define K1_SMEM_FLOATS 22096            // 88384 B

// ================= K1: fused logits + dispatch softmax + chunk colstats + partial xs ===
// grid (64, 8), 256 thr
extern "C" __global__ void __launch_bounds__(256)
k1_fused(const float* __restrict__ x, const float* __restrict__ phi) {
    extern __shared__ float smemf[];
    u64*   phiD = (u64*)(smemf + OFF_PHI);
    float* xT   = smemf + OFF_XT;
    u64*   red  = (u64*)(smemf + OFF_RED);
    float* lsm  = smemf + OFF_LSM;
    float* dsm  = smemf + OFF_DSM;
    float* gm   = smemf + OFF_GM;
    float* ps   = smemf + OFF_PS;
    float* cm   = smemf + OFF_CM;

    const int b = blockIdx.y, chunk = blockIdx.x;
    const int tid = threadIdx.x;
    const float* xc = x + ((size_t)b * Nc + chunk * TOK1) * Dc;

    {   // phi [768][16] -> u64 pairs, straight copy
        const u64* ph = (const u64*)phi;
        for (int i = tid; i < Dc * 8; i += 256) phiD[i] = ph[i];
    }

    // ---- Phase A: logits. thread = (tok 0..63, seg 0..3); seg covers 16 d per dblock --
    const int tok = tid & 63;
    const int seg = tid >> 6;
    u64 acc[8];
    #pragma unroll
    for (int j = 0; j < 8; ++j) acc[j] = 0ull;

    for (int db = 0; db < 12; ++db) {
        const int d0 = db * 64;
        __syncthreads();
        // stage x[64 tok][64 d] transposed via float4 loads
        #pragma unroll
        for (int k = 0; k < 4; ++k) {
            const int idx = tid + k * 256;          // 0..1023
            const int t = idx >> 4, dd4 = idx & 15;
            const float4 v = __ldg((const float4*)(xc + (size_t)t * Dc + d0 + dd4 * 4));
            xT[(dd4 * 4 + 0) * 65 + t] = v.x;
            xT[(dd4 * 4 + 1) * 65 + t] = v.y;
            xT[(dd4 * 4 + 2) * 65 + t] = v.z;
            xT[(dd4 * 4 + 3) * 65 + t] = v.w;
        }
        __syncthreads();
        const ulonglong2* pp = (const ulonglong2*)phiD;
        #pragma unroll 4
        for (int i = 0; i < 16; ++i) {
            const int dd = seg * 16 + i;
            const int d = d0 + dd;
            const u64 xd = dup2(xT[dd * 65 + tok]);
            ulonglong2 q0 = pp[d * 4 + 0];
            ulonglong2 q1 = pp[d * 4 + 1];
            ulonglong2 q2 = pp[d * 4 + 2];
            ulonglong2 q3 = pp[d * 4 + 3];
            fma2(acc[0], xd, q0.x); fma2(acc[1], xd, q0.y);
            fma2(acc[2], xd, q1.x); fma2(acc[3], xd, q1.y);
            fma2(acc[4], xd, q2.x); fma2(acc[5], xd, q2.y);
            fma2(acc[6], xd, q3.x); fma2(acc[7], xd, q3.y);
        }
    }
    __syncthreads();
    if (seg > 0) {
        u64* r = red + ((seg - 1) * 64 + tok) * 8;
        #pragma unroll
        for (int j = 0; j < 8; ++j) r[j] = acc[j];
    }
    __syncthreads();
    if (seg == 0) {
        #pragma unroll
        for (int q = 0; q < 3; ++q) {
            const u64* r = red + (q * 64 + tok) * 8;
            #pragma unroll
            for (int j = 0; j < 8; ++j) acc[j] = add2(acc[j], r[j]);
        }
        float l[16];
        #pragma unroll
        for (int j = 0; j < 8; ++j) up2(acc[j], l[2 * j], l[2 * j + 1]);
        float m = l[0];
        #pragma unroll
        for (int es = 1; es < 16; ++es) m = fmaxf(m, l[es]);
        float s = 0.f;
        float p[16];
        #pragma unroll
        for (int es = 0; es < 16; ++es) { p[es] = __expf(l[es] - m); s += p[es]; }
        const float inv = 1.f / s;
        u64* dl = (u64*)dsm;
        u64* ll = (u64*)lsm;
        #pragma unroll
        for (int j = 0; j < 8; ++j) {
            dl[tok * 8 + j] = pk2(p[2 * j] * inv, p[2 * j + 1] * inv);
            ll[tok * 8 + j] = pk2(l[2 * j], l[2 * j + 1]);
        }
    }
    __syncthreads();

    {   // raw logits -> global
        const size_t lbase = ((size_t)b * Nc + chunk * TOK1) * ESc;
        #pragma unroll
        for (int k = 0; k < 4; ++k) g_logits[lbase + tid + k * 256] = lsm[tid + k * 256];
    }

    // ---- Phase B: per-chunk column stats (16 groups x 4 tokens) ----
    {
        const int g = tid >> 4, es = tid & 15;
        float m = -1e30f;
        #pragma unroll
        for (int t4 = 0; t4 < 4; ++t4) m = fmaxf(m, lsm[(g * 4 + t4) * ESc + es]);
        gm[g * 16 + es] = m;
    }
    __syncthreads();
    if (tid < 16) {
        float m = gm[tid];
        #pragma unroll
        for (int g = 1; g < 16; ++g) m = fmaxf(m, gm[g * 16 + tid]);
        cm[tid] = m;
    }
    __syncthreads();
    {
        const int g = tid >> 4, es = tid & 15;
        const float m = cm[es];
        float p = 0.f;
        #pragma unroll
        for (int t4 = 0; t4 < 4; ++t4) p += __expf(lsm[(g * 4 + t4) * ESc + es] - m);
        ps[g * 16 + es] = p;
    }
    __syncthreads();
    if (tid < 16) {
        float s = 0.f;
        #pragma unroll
        for (int g = 0; g < 16; ++g) s += ps[g * 16 + tid];
        g_mch[((size_t)b * NCH1 + chunk) * ESc + tid] = cm[tid];
        g_sch[((size_t)b * NCH1 + chunk) * ESc + tid] = s;
    }

    // ---- Phase C: partial xs, thread = (12 d as 3 float4) x (4 es) ----
    {
        const int f4i = tid & 63;
        const int esq = tid >> 6;
        u64 acc2[4][3][2];
        #pragma unroll
        for (int e = 0; e < 4; ++e)
            #pragma unroll
            for (int j = 0; j < 3; ++j) { acc2[e][j][0] = 0ull; acc2[e][j][1] = 0ull; }

        const int dbase = f4i * 4;
        #pragma unroll 2
        for (int t = 0; t < TOK1; ++t) {
            const float4 xv0 = __ldg((const float4*)(xc + (size_t)t * Dc + dbase));
            const float4 xv1 = __ldg((const float4*)(xc + (size_t)t * Dc + dbase + 256));
            const float4 xv2 = __ldg((const float4*)(xc + (size_t)t * Dc + dbase + 512));
            const u64 x0l = pk2(xv0.x, xv0.y), x0h = pk2(xv0.z, xv0.w);
            const u64 x1l = pk2(xv1.x, xv1.y), x1h = pk2(xv1.z, xv1.w);
            const u64 x2l = pk2(xv2.x, xv2.y), x2h = pk2(xv2.z, xv2.w);
            const float4 dv = *(const float4*)&dsm[t * ESc + esq * 4];
            const u64 w0 = dup2(dv.x), w1 = dup2(dv.y), w2 = dup2(dv.z), w3 = dup2(dv.w);
            fma2(acc2[0][0][0], w0, x0l); fma2(acc2[0][0][1], w0, x0h);
            fma2(acc2[0][1][0], w0, x1l); fma2(acc2[0][1][1], w0, x1h);
            fma2(acc2[0][2][0], w0, x2l); fma2(acc2[0][2][1], w0, x2h);
            fma2(acc2[1][0][0], w1, x0l); fma2(acc2[1][0][1], w1, x0h);
            fma2(acc2[1][1][0], w1, x1l); fma2(acc2[1][1][1], w1, x1h);
            fma2(acc2[1][2][0], w1, x2l); fma2(acc2[1][2][1], w1, x2h);
            fma2(acc2[2][0][0], w2, x0l); fma2(acc2[2][0][1], w2, x0h);
            fma2(acc2[2][1][0], w2, x1l); fma2(acc2[2][1][1], w2, x1h);
            fma2(acc2[2][2][0], w2, x2l); fma2(acc2[2][2][1], w2, x2h);
            fma2(acc2[3][0][0], w3, x0l); fma2(acc2[3][0][1], w3, x0h);
            fma2(acc2[3][1][0], w3, x1l); fma2(acc2[3][1][1], w3, x1h);
            fma2(acc2[3][2][0], w3, x2l); fma2(acc2[3][2][1], w3, x2h);
        }
        float* out = g_pxs + ((size_t)(b * NCH1 + chunk) * ESc) * Dc;
        #pragma unroll
        for (int e = 0; e < 4; ++e) {
            const int es = esq * 4 + e;
            #pragma unroll
            for (int j = 0; j < 3; ++j) {
                float4 o;
                up2(acc2[e][j][0], o.x, o.y);
                up2(acc2[e][j][1], o.z, o.w);
                *(float4*)(out + (size_t)es * Dc + dbase + 256 * j) = o;
            }
        }
    }
}

// ================= K2: reduce xs partials + pack row pairs =================
__global__ void __launch_bounds__(256) k2_reduce_xs() {
    const int idx = blockIdx.x * 256 + threadIdx.x;
    const int b = idx / (ESc * Dc);
    const int rem = idx % (ESc * Dc);
    const int es = rem / Dc, d = rem % Dc;
    float s = 0.f;
    #pragma unroll 8
    for (int c = 0; c < NCH1; ++c)
        s += g_pxs[((size_t)(b * NCH1 + c)) * (ESc * Dc) + rem];
    const int e = es >> 1, sl = es & 1, row = b * 2 + sl;
    ((float*)g_xs2)[((size_t)e * Dc + d) * 16 + row] = s;
}

// ================= K4: finalize colmax / inv colsum =================
__global__ void k4_finalize() {
    const int i = threadIdx.x;
    if (i >= Bc * ESc) return;
    const int b = i >> 4, es = i & 15;
    float M = -1e30f;
    #pragma unroll 8
    for (int c = 0; c < NCH1; ++c)
        M = fmaxf(M, g_mch[((size_t)b * NCH1 + c) * ESc + es]);
    float S = 0.f;
    #pragma unroll 8
    for (int c = 0; c < NCH1; ++c) {
        const size_t o = ((size_t)b * NCH1 + c) * ESc + es;
        S += __expf(g_mch[o] - M) * g_sch[o];
    }
    g_cmaxf[i] = M;
    g_inv[i] = 1.f / S;
}

// ================= K5: FFN1 + GELU  (grid (48, 8), 256 thr) =================
// thread: fi=t&15 (4 f), rh=(t>>4)&1 (4 row-pairs), ds=t>>5 (8 segs of 96 d)
#define K5_SMEM_BYTES (Dc * 8 * 8 + 2048 * 8)   // 49152 + 16384 = 65536
__global__ void __launch_bounds__(256, 3)
k5_ffn1(const float* __restrict__ w1, const float* __restrict__ b1) {
    extern __shared__ __align__(16) char k5smem[];
    u64* xsm = (u64*)k5smem;             // Dc*8
    u64* red = xsm + Dc * 8;             // 2048
    const int e = blockIdx.y;
    const int fbase = blockIdx.x * 64;
    const int tid = threadIdx.x;
    {
        const ulonglong2* src = (const ulonglong2*)(g_xs2 + (size_t)e * Dc * 8);
        ulonglong2* dst = (ulonglong2*)xsm;
        #pragma unroll
        for (int k = 0; k < 12; ++k) dst[tid + k * 256] = src[tid + k * 256];
    }
    __syncthreads();

    const int fi = tid & 15;
    const int rh = (tid >> 4) & 1;
    const int ds = tid >> 5;
    const int lid32 = tid & 31;
    const int f = fbase + fi * 4;

    u64 acc[4][4];
    #pragma unroll
    for (int j = 0; j < 4; ++j)
        #pragma unroll
        for (int r = 0; r < 4; ++r) acc[j][r] = 0ull;

    const float* w = w1 + (size_t)e * Dc * Hc + f;
    const ulonglong2* x2 = (const ulonglong2*)xsm;
    const int dlo = ds * 96;
    #pragma unroll 8
    for (int d = dlo; d < dlo + 96; ++d) {
        const float4 wv = __ldg((const float4*)(w + (size_t)d * Hc));
        const ulonglong2 xa = x2[d * 4 + rh * 2];
        const ulonglong2 xb = x2[d * 4 + rh * 2 + 1];
        const u64 w0 = dup2(wv.x), w1d = dup2(wv.y), w2 = dup2(wv.z), w3 = dup2(wv.w);
        fma2(acc[0][0], w0, xa.x); fma2(acc[0][1], w0, xa.y);
        fma2(acc[0][2], w0, xb.x); fma2(acc[0][3], w0, xb.y);
        fma2(acc[1][0], w1d, xa.x); fma2(acc[1][1], w1d, xa.y);
        fma2(acc[1][2], w1d, xb.x); fma2(acc[1][3], w1d, xb.y);
        fma2(acc[2][0], w2, xa.x); fma2(acc[2][1], w2, xa.y);
        fma2(acc[2][2], w2, xb.x); fma2(acc[2][3], w2, xb.y);
        fma2(acc[3][0], w3, xa.x); fma2(acc[3][1], w3, xa.y);
        fma2(acc[3][2], w3, xb.x); fma2(acc[3][3], w3, xb.y);
    }

    // tree reduce over 8 d-segs
    if (ds >= 4) {
        u64* r = red + ((ds - 4) * 32 + lid32) * 16;
        #pragma unroll
        for (int j = 0; j < 4; ++j)
            #pragma unroll
            for (int k = 0; k < 4; ++k) r[j * 4 + k] = acc[j][k];
    }
    __syncthreads();
    if (ds < 4) {
        const u64* r = red + (ds * 32 + lid32) * 16;
        #pragma unroll
        for (int j = 0; j < 4; ++j)
            #pragma unroll
            for (int k = 0; k < 4; ++k) acc[j][k] = add2(acc[j][k], r[j * 4 + k]);
    }
    __syncthreads();
    if (ds >= 2 && ds < 4) {
        u64* r = red + ((ds - 2) * 32 + lid32) * 16;
        #pragma unroll
        for (int j = 0; j < 4; ++j)
            #pragma unroll
            for (int k = 0; k < 4; ++k) r[j * 4 + k] = acc[j][k];
    }
    __syncthreads();
    if (ds < 2) {
        const u64* r = red + (ds * 32 + lid32) * 16;
        #pragma unroll
        for (int j = 0; j < 4; ++j)
            #pragma unroll
            for (int k = 0; k < 4; ++k) acc[j][k] = add2(acc[j][k], r[j * 4 + k]);
    }
    __syncthreads();
    if (ds == 1) {
        u64* r = red + lid32 * 16;
        #pragma unroll
        for (int j = 0; j < 4; ++j)
            #pragma unroll
            for (int k = 0; k < 4; ++k) r[j * 4 + k] = acc[j][k];
    }
    __syncthreads();
    if (ds == 0) {
        u64* r = red + lid32 * 16;
        #pragma unroll
        for (int j = 0; j < 4; ++j)
            #pragma unroll
            for (int k = 0; k < 4; ++k) r[j * 4 + k] = add2(acc[j][k], r[j * 4 + k]);
    }
    __syncthreads();
    // distributed GELU epilogue: 512 u64, 2 per thread
    #pragma unroll
    for (int q = 0; q < 2; ++q) {
        const int flat = tid * 2 + q;
        const int t32 = flat >> 4, j = flat & 15;
        const int fi2 = t32 & 15, rh2 = t32 >> 4;
        const int jf = j >> 2, jr = j & 3;
        const int f2 = fbase + fi2 * 4 + jf;
        const int rp = rh2 * 4 + jr;
        const float bv = __ldg(b1 + (size_t)e * Hc + f2);
        float lo, hi; up2(red[flat], lo, hi);
        g_h2[((size_t)e * Hc + f2) * 8 + rp] =
            pk2(gelu_exact(lo + bv), gelu_exact(hi + bv));
    }
}

// ================= K6: FFN2 + bias  (grid (48, 8), 256 thr) =================
__global__ void __launch_bounds__(256, 3)
k6_ffn2(const float* __restrict__ w2, const float* __restrict__ b2) {
    __shared__ __align__(16) u64 red[32 * 128];    // 32KB
    const int e = blockIdx.y;
    const int d0 = blockIdx.x * 16;
    const int tid = threadIdx.x;
    const int dq = tid & 3, rh = (tid >> 2) & 1, fs = tid >> 3;

    u64 acc[4][4];
    #pragma unroll
    for (int j = 0; j < 4; ++j)
        #pragma unroll
        for (int r = 0; r < 4; ++r) acc[j][r] = 0ull;

    const float* w = w2 + (size_t)e * Hc * Dc + d0 + dq * 4;
    const ulonglong2* h2 = (const ulonglong2*)(g_h2 + (size_t)e * Hc * 8);
    const int f0 = fs * 96;
    #pragma unroll 8
    for (int f = f0; f < f0 + 96; ++f) {
        const float4 wv = __ldg((const float4*)(w + (size_t)f * Dc));
        const ulonglong2 ha = h2[f * 4 + rh * 2];
        const ulonglong2 hb = h2[f * 4 + rh * 2 + 1];
        const u64 wd0 = dup2(wv.x), wd1 = dup2(wv.y), wd2 = dup2(wv.z), wd3 = dup2(wv.w);
        fma2(acc[0][0], wd0, ha.x); fma2(acc[0][1], wd0, ha.y);
        fma2(acc[0][2], wd0, hb.x); fma2(acc[0][3], wd0, hb.y);
        fma2(acc[1][0], wd1, ha.x); fma2(acc[1][1], wd1, ha.y);
        fma2(acc[1][2], wd1, hb.x); fma2(acc[1][3], wd1, hb.y);
        fma2(acc[2][0], wd2, ha.x); fma2(acc[2][1], wd2, ha.y);
        fma2(acc[2][2], wd2, hb.x); fma2(acc[2][3], wd2, hb.y);
        fma2(acc[3][0], wd3, ha.x); fma2(acc[3][1], wd3, ha.y);
        fma2(acc[3][2], wd3, hb.x); fma2(acc[3][3], wd3, hb.y);
    }
    #pragma unroll
    for (int j = 0; j < 4; ++j)
        #pragma unroll
        for (int r = 0; r < 4; ++r)
            red[fs * 128 + (dq * 4 + j) * 8 + rh * 4 + r] = acc[j][r];
    __syncthreads();
    if (tid < 128) {
        const int d_loc = tid >> 3, rp = tid & 7;
        u64 s = red[d_loc * 8 + rp];
        #pragma unroll 8
        for (int f2 = 1; f2 < 32; ++f2) s = add2(s, red[f2 * 128 + d_loc * 8 + rp]);
        float lo, hi; up2(s, lo, hi);
        const float bb2 = __ldg(b2 + (size_t)e * Dc + d0 + d_loc);
        const int r0 = 2 * rp, r1 = 2 * rp + 1;
        g_ys[((size_t)(r0 >> 1) * ESc + e * 2 + (r0 & 1)) * Dc + d0 + d_loc] = lo + bb2;
        g_ys[((size_t)(r1 >> 1) * ESc + e * 2 + (r1 & 1)) * Dc + d0 + d_loc] = hi + bb2;
    }
}

// ================= K7: combine softmax + y = c @ ys  (grid (64, 8)) =================
#define K7_SMEM_FLOATS (ESc * Dc + ESc * TOK7 + 32)
extern "C" __global__ void __launch_bounds__(256)
k7_combine(float* __restrict__ y) {
    extern __shared__ float smemf[];
    float* ysm = smemf;                       // [16][768]
    float* csm = smemf + ESc * Dc;            // [16][64]
    float* cm  = smemf + ESc * Dc + ESc * TOK7;
    float* inv = cm + 16;

    const int b = blockIdx.y, chunk = blockIdx.x, tid = threadIdx.x;
    {
        const float4* src = (const float4*)(g_ys + (size_t)b * ESc * Dc);
        float4* dst = (float4*)ysm;
        #pragma unroll
        for (int k = 0; k < 12; ++k) dst[tid + k * 256] = src[tid + k * 256];
    }
    if (tid < 16) { cm[tid] = g_cmaxf[b * ESc + tid]; inv[tid] = g_inv[b * ESc + tid]; }
    __syncthreads();

    {   // combine weights: 1024 entries, 4 per thread
        const int i0 = tid * 4;
        const int es = i0 >> 6;
        const int t0 = i0 & 63;
        const float m = cm[es], iv = inv[es];
        const float* lp = g_logits + ((size_t)b * Nc + chunk * TOK7 + t0) * ESc + es;
        #pragma unroll
        for (int q = 0; q < 4; ++q)
            csm[es * TOK7 + t0 + q] = __expf(lp[q * ESc] - m) * iv;
    }
    __syncthreads();

    const int dg = tid & 63, tg = tid >> 6;
    const int dbase = dg * 4;
    float* yb = y + ((size_t)b * Nc + chunk * TOK7) * Dc;
    for (int tq = 0; tq < 4; ++tq) {
        const int trel = tg * 16 + tq * 4;
        u64 acc[4][3][2];
        #pragma unroll
        for (int t = 0; t < 4; ++t)
            #pragma unroll
            for (int j = 0; j < 3; ++j) { acc[t][j][0] = 0ull; acc[t][j][1] = 0ull; }
        #pragma unroll
        for (int es = 0; es < 16; ++es) {
            float4 c4 = *(const float4*)&csm[es * TOK7 + trel];
            u64 cd0 = dup2(c4.x), cd1 = dup2(c4.y), cd2 = dup2(c4.z), cd3 = dup2(c4.w);
            #pragma unroll
            for (int j = 0; j < 3; ++j) {
                float4 yv = *(const float4*)&ysm[es * Dc + dbase + 256 * j];
                u64 ylo = pk2(yv.x, yv.y), yhi = pk2(yv.z, yv.w);
                fma2(acc[0][j][0], cd0, ylo); fma2(acc[0][j][1], cd0, yhi);
                fma2(acc[1][j][0], cd1, ylo); fma2(acc[1][j][1], cd1, yhi);
                fma2(acc[2][j][0], cd2, ylo); fma2(acc[2][j][1], cd2, yhi);
                fma2(acc[3][j][0], cd3, ylo); fma2(acc[3][j][1], cd3, yhi);
            }
        }
        #pragma unroll
        for (int t = 0; t < 4; ++t) {
            float* yr = yb + (size_t)(trel + t) * Dc;
            #pragma unroll
            for (int j = 0; j < 3; ++j) {
                float4 o;
                up2(acc[t][j][0], o.x, o.y);
                up2(acc[t][j][1], o.z, o.w);
                *(float4*)(yr + dbase + 256 * j) = o;
            }
        }
    }
}

// ================= host =================
extern "C" void kernel_launch(void* const* d_in, const int* in_sizes, int n_in,
                              void* d_out, int out_size) {
    const float* x   = (const float*)d_in[0];
    const float* phi = (const float*)d_in[1];
    const float* w1  = (const float*)d_in[2];
    const float* b1  = (const float*)d_in[3];
    const float* w2  = (const float*)d_in[4];
    const float* b2  = (const float*)d_in[5];
    float* y = (float*)d_out;

    cudaFuncSetAttribute(k1_fused, cudaFuncAttributeMaxDynamicSharedMemorySize,
                         K1_SMEM_FLOATS * sizeof(float));
    cudaFuncSetAttribute(k5_ffn1, cudaFuncAttributeMaxDynamicSharedMemorySize,
                         K5_SMEM_BYTES);
    cudaFuncSetAttribute(k7_combine, cudaFuncAttributeMaxDynamicSharedMemorySize,
                         K7_SMEM_FLOATS * sizeof(float));
    (void)in_sizes; (void)n_in; (void)out_size;

    k1_fused<<<dim3(NCH1, Bc), 256, K1_SMEM_FLOATS * sizeof(float)>>>(x, phi);
    k2_reduce_xs<<<(Bc * ESc * Dc) / 256, 256>>>();
    k4_finalize<<<1, 128>>>();
    k5_ffn1<<<dim3(Hc / 64, Ec), 256, K5_SMEM_BYTES>>>(w1, b1);
    k6_ffn2<<<dim3(Dc / 16, Ec), 256>>>(w2, b2);
    k7_combine<<<dim3(Nc / TOK7, Bc), 256, K7_SMEM_FLOATS * sizeof(float)>>>(y);
}